// round 9
// baseline (speedup 1.0000x reference)
#include <cuda_runtime.h>
#include <cstdint>

// Problem constants (fixed shapes in reference_code)
#define BB     1024
#define CC     20
#define NN     26
#define VDIM   128
#define NSPL   10
#define NWORDS 100000

// Scores-only kernel. One block per batch row.
// scores[b,n] = sum_v x[b,v] * O[v, tgt[b,n]]
// x[b,v] = (1/C) * sum_c ( D[knot[b], ctx[b,c], v] * x_vals[b] + W[ctx[b,c], v] )
__global__ void __launch_bounds__(256)
dmspline_scores(const float* __restrict__ x_vals,
                const int*   __restrict__ knot_ids,
                const int*   __restrict__ context_ids,
                const int*   __restrict__ target_ids,
                const float* __restrict__ D,
                const float* __restrict__ W,
                const float* __restrict__ O,
                float* __restrict__ out)
{
    __shared__ float sx[VDIM];
    __shared__ int   sctx[CC];

    const int bid = blockIdx.x;
    const int tid = threadIdx.x;

    // ---- stage context ids through shared ----
    if (tid < CC) sctx[tid] = context_ids[bid * CC + tid];
    __syncthreads();

    // ---- phase 1: x[v] for v = tid (threads 0..127) ----
    if (tid < VDIM) {
        const int   knot = knot_ids[bid];
        const float xv   = x_vals[bid];
        const float* __restrict__ Dk = D + (size_t)knot * NWORDS * VDIM;
        float acc = 0.0f;
        #pragma unroll
        for (int c = 0; c < CC; ++c) {
            const int ctx = sctx[c];
            const float d = __ldg(Dk + (size_t)ctx * VDIM + tid);
            const float w = __ldg(W  + (size_t)ctx * VDIM + tid);
            acc = fmaf(d, xv, acc) + w;
        }
        sx[tid] = acc * (1.0f / CC);
    }
    __syncthreads();

    // ---- phase 2: warp w handles n = w, w+8, w+16, w+24 (<= 4 each);
    // all O-gather loads front-loaded before any reduction ----
    const int warp = tid >> 5;
    const int lane = tid & 31;

    int nlist[4];
    int cnt = 0;
    #pragma unroll
    for (int n = warp; n < NN; n += 8) nlist[cnt++] = n;

    const float* __restrict__ ocol[4];
    #pragma unroll
    for (int i = 0; i < 4; ++i) {
        if (i < cnt) ocol[i] = O + target_ids[bid * NN + nlist[i]];
    }

    float ov[4][4];
    #pragma unroll
    for (int i = 0; i < 4; ++i) {
        if (i < cnt) {
            #pragma unroll
            for (int k = 0; k < 4; ++k) {
                ov[i][k] = __ldg(ocol[i] + (size_t)(lane + 32 * k) * NWORDS);
            }
        }
    }

    float xs[4];
    #pragma unroll
    for (int k = 0; k < 4; ++k) xs[k] = sx[lane + 32 * k];

    #pragma unroll
    for (int i = 0; i < 4; ++i) {
        if (i < cnt) {
            float s = 0.0f;
            #pragma unroll
            for (int k = 0; k < 4; ++k) s = fmaf(xs[k], ov[i][k], s);
            #pragma unroll
            for (int off = 16; off; off >>= 1)
                s += __shfl_down_sync(0xffffffffu, s, off);
            if (lane == 0) out[bid * NN + nlist[i]] = s;
        }
    }
}

extern "C" void kernel_launch(void* const* d_in, const int* in_sizes, int n_in,
                              void* d_out, int out_size)
{
    const float* x_vals      = (const float*)d_in[0];
    const int*   knot_ids    = (const int*)  d_in[1];
    const int*   context_ids = (const int*)  d_in[2];
    const int*   target_ids  = (const int*)  d_in[3];
    const float* D           = (const float*)d_in[4];
    const float* W           = (const float*)d_in[5];
    const float* O           = (const float*)d_in[6];
    float*       out         = (float*)d_out;

    // Lazily-created side stream + fork/join events (created on the first,
    // uncaptured, correctness call; reused every call -> identical captured
    // graph). No device memory is allocated anywhere.
    static cudaStream_t s2      = nullptr;
    static cudaEvent_t  ev_fork = nullptr;
    static cudaEvent_t  ev_join = nullptr;
    if (s2 == nullptr) {
        int prio_lo = 0, prio_hi = 0;
        cudaDeviceGetStreamPriorityRange(&prio_lo, &prio_hi);
        cudaStreamCreateWithPriority(&s2, cudaStreamNonBlocking, prio_lo);
        cudaEventCreateWithFlags(&ev_fork, cudaEventDisableTiming);
        cudaEventCreateWithFlags(&ev_join, cudaEventDisableTiming);
    }

    const long long dElems = (long long)NSPL * NWORDS * VDIM;   // 128,000,000
    const long long need   = (long long)BB * NN + dElems;
    const bool do_copy = ((long long)out_size >= need);

    const size_t half = (size_t)dElems / 2;                     // 64,000,000
    float* dstD = out + (size_t)BB * NN;

    if (do_copy) {
        // Fork chunk A (first half of D) onto the side stream so it can run
        // concurrently with the scores kernel (read-read on D; disjoint dst).
        cudaEventRecord(ev_fork, 0);
        cudaStreamWaitEvent(s2, ev_fork, 0);
        cudaMemcpyAsync(dstD, D, half * sizeof(float),
                        cudaMemcpyDeviceToDevice, s2);
        cudaEventRecord(ev_join, s2);
    }

    // Scores kernel on the main captured stream (overlaps chunk A if the
    // memcpy engine allows concurrency).
    dmspline_scores<<<BB, 256>>>(x_vals, knot_ids, context_ids, target_ids,
                                 D, W, O, out);

    if (do_copy) {
        // Chunk B (second half) on the main stream after the scores kernel.
        cudaMemcpyAsync(dstD + half, D + half, half * sizeof(float),
                        cudaMemcpyDeviceToDevice, 0);
        // Join: completion requires chunk A as well.
        cudaStreamWaitEvent(0, ev_join, 0);
    }
}